// round 12
// baseline (speedup 1.0000x reference)
#include <cuda_runtime.h>

// DynamicUpsamplingFilter — warp=1u x 32wq remap: each warp LDG covers 512B
// contiguous (vs 2x256B), testing DRAM row-buffer-locality as the residual.
//   x:       (4, 3, 180, 320) f32
//   filters: (4, 25, 16, 180, 320) f32
//   out:     (4, 48, 180, 320) f32
//   out[n, c*16+u, h, w] = sum_p x_pad[n, c, h+p/5-2, w+p%5-2] * filters[n, p, u, h, w]

#define NN 4
#define CC 3
#define HH 180
#define WW 320
#define UU 16
#define KH 5
#define KW 5
#define PP (KH*KW)
#define TILE_W 128
#define WT 3                    // w-tiles: 128,128,64 (ragged)
#define SROW 132                // TILE_W + 4 halo
#define XELEMS (CC * KH * SROW) // 1980 smem elements

__global__ void __launch_bounds__(256, 5)
duf_kernel(const float* __restrict__ x,
           const float* __restrict__ filters,
           float* __restrict__ out) {
    // Block: (n, h, w-tile of <=128, u-half). 256 threads = 8 u x 32 wq.
    // A warp is ONE u and 32 consecutive float4 quads -> 512B contiguous/LDG.
    __shared__ float sx[CC][KH][SROW];  // 7920 B

    const int wq = threadIdx.x & 31;                       // 0..31
    const int uh = blockIdx.x & 1;                         // u half
    const int wt = blockIdx.x >> 1;                        // 0..2
    const int u  = (threadIdx.x >> 5) + (uh << 3);         // 0..15
    const int wb = wt * TILE_W;
    const int h  = blockIdx.y;
    const int n  = blockIdx.z;

    const int w0   = wb + wq * 4;
    const bool act = (w0 < WW);                 // lane owns real output?
    const int w0c  = act ? w0 : (WW - 4);       // clamped (warp-merged) addr
    const float* fp = filters + ((((size_t)n * PP) * UU + u) * HH + h) * WW + w0c;
    const size_t PS = (size_t)UU * HH * WW;     // p-plane stride (elements)

    // ---- (1) x-tile loads FIRST (L2 hits ahead of filter DRAM misses in
    //      the L1tex FIFO -> barrier releases on x latency)
    float xv[8];
    #pragma unroll
    for (int k = 0; k < 8; ++k) {
        const int e = threadIdx.x + k * 256;
        float v = 0.0f;
        if (e < XELEMS) {
            const int pos = e % SROW;
            const int t   = e / SROW;
            const int i   = t % KH;
            const int c   = t / KH;
            const int col = wb + pos - 2;
            const int row = h + i - 2;
            if ((unsigned)col < WW && (unsigned)row < HH)
                v = x[((n * CC + c) * HH + row) * WW + col];
        }
        xv[k] = v;
    }

    // ---- (2) hoist filter row 0 (stream in flight during the fill)
    float4 cur[KW];
    #pragma unroll
    for (int j = 0; j < KW; ++j)
        cur[j] = __ldcs(reinterpret_cast<const float4*>(fp + (size_t)j * PS));

    // ---- (3) store x tile + barrier (waits only on the x loads)
    float* sflat = &sx[0][0][0];
    #pragma unroll
    for (int k = 0; k < 8; ++k) {
        const int e = threadIdx.x + k * 256;
        if (e < XELEMS) sflat[e] = xv[k];
    }
    __syncthreads();

    float4 acc[CC];
    #pragma unroll
    for (int c = 0; c < CC; ++c) acc[c] = make_float4(0.f, 0.f, 0.f, 0.f);

    // ---- (4) rolling pipeline: consume tap j, refill slot j with row i+1
    #pragma unroll
    for (int i = 0; i < KH; ++i) {
        float4 win[CC];
        #pragma unroll
        for (int c = 0; c < CC; ++c)
            win[c] = *reinterpret_cast<const float4*>(&sx[c][i][wq * 4]);

        #pragma unroll
        for (int j = 0; j < KW; ++j) {
            #pragma unroll
            for (int c = 0; c < CC; ++c) {
                acc[c].x = fmaf(win[c].x, cur[j].x, acc[c].x);
                acc[c].y = fmaf(win[c].y, cur[j].y, acc[c].y);
                acc[c].z = fmaf(win[c].z, cur[j].z, acc[c].z);
                acc[c].w = fmaf(win[c].w, cur[j].w, acc[c].w);
            }
            if (i < KH - 1)
                cur[j] = __ldcs(reinterpret_cast<const float4*>(
                    fp + (size_t)((i + 1) * KW + j) * PS));
            if (j < KW - 1) {
                #pragma unroll
                for (int c = 0; c < CC; ++c) {
                    const float nw = sx[c][i][wq * 4 + j + 4];
                    win[c] = make_float4(win[c].y, win[c].z, win[c].w, nw);
                }
            }
        }
    }

    // ---- store (predicated on lane activity): out[n, c*16+u, h, w0..w0+3]
    if (act) {
        #pragma unroll
        for (int c = 0; c < CC; ++c) {
            float4* optr = reinterpret_cast<float4*>(
                out + ((((size_t)n * (CC * UU)) + c * UU + u) * HH + h) * WW + w0);
            __stcs(optr, acc[c]);
        }
    }
}

extern "C" void kernel_launch(void* const* d_in, const int* in_sizes, int n_in,
                              void* d_out, int out_size) {
    const float* x       = (const float*)d_in[0];
    const float* filters = (const float*)d_in[1];
    float* out           = (float*)d_out;

    dim3 grid(WT * 2, HH, NN);  // (6, 180, 4) = 4320 blocks
    dim3 block(256);
    duf_kernel<<<grid, block>>>(x, filters, out);
}

// round 13
// speedup vs baseline: 1.0614x; 1.0614x over previous
#include <cuda_runtime.h>

// DynamicUpsamplingFilter — R8 champion (x-first L1tex ordering, rows 0+1
// hoisted through the fill window) + smooth per-tap rolling refill:
//   x:       (4, 3, 180, 320) f32
//   filters: (4, 25, 16, 180, 320) f32
//   out:     (4, 48, 180, 320) f32
//   out[n, c*16+u, h, w] = sum_p x_pad[n, c, h+p/5-2, w+p%5-2] * filters[n, p, u, h, w]

#define NN 4
#define CC 3
#define HH 180
#define WW 320
#define UU 16
#define KH 5
#define KW 5
#define PP (KH*KW)
#define TILE_W 64
#define SROW 68                 // TILE_W + 4 halo
#define XELEMS (CC * KH * SROW) // 1020 smem elements

__global__ void __launch_bounds__(256, 4)
duf_kernel(const float* __restrict__ x,
           const float* __restrict__ filters,
           float* __restrict__ out) {
    // Block: one (n, h, w-tile of 64). 256 threads = 16 u-values x 16 w-quads.
    __shared__ float sx[CC][KH][SROW];  // 4080 B

    const int wq = threadIdx.x & 15;
    const int u  = threadIdx.x >> 4;
    const int wb = blockIdx.x * TILE_W;
    const int h  = blockIdx.y;
    const int n  = blockIdx.z;

    const int w0 = wb + wq * 4;
    const float* fp = filters + ((((size_t)n * PP) * UU + u) * HH + h) * WW + w0;
    const size_t PS = (size_t)UU * HH * WW;  // p-plane stride (elements)

    // ---- (1) x-tile loads FIRST (L2 hits sit ahead of the filter DRAM
    //      misses in the L1tex FIFO -> barrier releases on x latency)
    float xv[4];
    #pragma unroll
    for (int k = 0; k < 4; ++k) {
        const int e = threadIdx.x + k * 256;
        float v = 0.0f;
        if (e < XELEMS) {
            const int pos = e % SROW;
            const int t   = e / SROW;
            const int i   = t % KH;
            const int c   = t / KH;
            const int col = wb + pos - 2;
            const int row = h + i - 2;
            if ((unsigned)col < WW && (unsigned)row < HH)
                v = x[((n * CC + c) * HH + row) * WW + col];
        }
        xv[k] = v;
    }

    // ---- (2) hoist filter rows 0 AND 1: 10 LDG.128 in flight during fill
    float4 cur[KW], nxt[KW];
    #pragma unroll
    for (int j = 0; j < KW; ++j)
        cur[j] = __ldcs(reinterpret_cast<const float4*>(fp + (size_t)j * PS));
    #pragma unroll
    for (int j = 0; j < KW; ++j)
        nxt[j] = __ldcs(reinterpret_cast<const float4*>(fp + (size_t)(KW + j) * PS));

    // ---- (3) store x tile + barrier (waits only on the x loads)
    float* sflat = &sx[0][0][0];
    #pragma unroll
    for (int k = 0; k < 4; ++k) {
        const int e = threadIdx.x + k * 256;
        if (e < XELEMS) sflat[e] = xv[k];
    }
    __syncthreads();

    float4 acc[CC];
    #pragma unroll
    for (int c = 0; c < CC; ++c) acc[c] = make_float4(0.f, 0.f, 0.f, 0.f);

    // ---- (4) steady loop, smooth depth-2 rolling refill: consume cur[j],
    //      rotate nxt[j] into it, refill nxt[j] with row i+2 — per tap, so
    //      in-flight load count stays ~10 instead of sawtoothing 5..10.
    #pragma unroll
    for (int i = 0; i < KH; ++i) {
        #pragma unroll
        for (int c = 0; c < CC; ++c) {
            const float4 a = *reinterpret_cast<const float4*>(&sx[c][i][wq * 4]);
            const float4 b = *reinterpret_cast<const float4*>(&sx[c][i][wq * 4 + 4]);
            const float pr[8] = {a.x, a.y, a.z, a.w, b.x, b.y, b.z, b.w};
            #pragma unroll
            for (int j = 0; j < KW; ++j) {
                acc[c].x = fmaf(pr[j + 0], cur[j].x, acc[c].x);
                acc[c].y = fmaf(pr[j + 1], cur[j].y, acc[c].y);
                acc[c].z = fmaf(pr[j + 2], cur[j].z, acc[c].z);
                acc[c].w = fmaf(pr[j + 3], cur[j].w, acc[c].w);
                // after the LAST channel consumes cur[j], rotate + refill it
                if (c == CC - 1 && i < KH - 1) {
                    cur[j] = nxt[j];
                    if (i < KH - 2)
                        nxt[j] = __ldcs(reinterpret_cast<const float4*>(
                            fp + (size_t)((i + 2) * KW + j) * PS));
                }
            }
        }
    }

    // ---- store: out[n, c*16+u, h, w0..w0+3] ----
    #pragma unroll
    for (int c = 0; c < CC; ++c) {
        float4* optr = reinterpret_cast<float4*>(
            out + ((((size_t)n * (CC * UU)) + c * UU + u) * HH + h) * WW + w0);
        __stcs(optr, acc[c]);
    }
}

extern "C" void kernel_launch(void* const* d_in, const int* in_sizes, int n_in,
                              void* d_out, int out_size) {
    const float* x       = (const float*)d_in[0];
    const float* filters = (const float*)d_in[1];
    float* out           = (float*)d_out;

    dim3 grid(WW / TILE_W, HH, NN);  // (5, 180, 4) = 3600 blocks
    dim3 block(256);
    duf_kernel<<<grid, block>>>(x, filters, out);
}